// round 2
// baseline (speedup 1.0000x reference)
#include <cuda_runtime.h>
#include <cstdint>
#include <cstddef>

#define T_STEPS 256
#define BATCH   32
#define EMB     256
#define LAT     512
#define OUT_DIM 32000
#define MROWS   (T_STEPS * BATCH)   // 8192

// ---------------- device scratch (no allocations allowed) ------------------
__device__ float    g_xproj[(size_t)MROWS * LAT];   // 16 MB
__device__ unsigned g_cnt[8];                        // per batch-group arrival counter

// ---------------- small asm helpers ----------------------------------------
__device__ __forceinline__ unsigned long long pack2(float a, float b) {
    unsigned long long r;
    asm("mov.b64 %0, {%1, %2};" : "=l"(r) : "f"(a), "f"(b));
    return r;
}
__device__ __forceinline__ void unpack2(unsigned long long v, float& a, float& b) {
    asm("mov.b64 {%0, %1}, %2;" : "=f"(a), "=f"(b) : "l"(v));
}
__device__ __forceinline__ void ffma2(unsigned long long& acc, unsigned long long h,
                                      unsigned long long w) {
    asm("fma.rn.f32x2 %0, %1, %2, %0;" : "+l"(acc) : "l"(h), "l"(w));
}
__device__ __forceinline__ uint32_t cvt_tf32(float f) {
    uint32_t o;
    asm("cvt.rna.tf32.f32 %0, %1;" : "=r"(o) : "f"(f));
    return o;
}
__device__ __forceinline__ uint32_t smaddr(const void* p) {
    return (uint32_t)__cvta_generic_to_shared(p);
}
__device__ __forceinline__ void cp_async16(uint32_t dst, const void* src) {
    asm volatile("cp.async.cg.shared.global [%0], [%1], 16;" :: "r"(dst), "l"(src));
}
__device__ __forceinline__ void cp_commit() {
    asm volatile("cp.async.commit_group;");
}
template <int N> __device__ __forceinline__ void cp_wait() {
    asm volatile("cp.async.wait_group %0;" :: "n"(N));
}
__device__ __forceinline__ void mma_tf32(float& c0, float& c1, float& c2, float& c3,
                                         uint32_t a0, uint32_t a1, uint32_t a2, uint32_t a3,
                                         uint32_t b0, uint32_t b1) {
    asm volatile(
        "mma.sync.aligned.m16n8k8.row.col.f32.tf32.tf32.f32 "
        "{%0,%1,%2,%3}, {%4,%5,%6,%7}, {%8,%9}, {%0,%1,%2,%3};"
        : "+f"(c0), "+f"(c1), "+f"(c2), "+f"(c3)
        : "r"(a0), "r"(a1), "r"(a2), "r"(a3), "r"(b0), "r"(b1));
}

// ============================================================================
// Kernel 1: xproj[r][l] = sum_e emb[x[r]][e] * W_h[e][l] + b_h[l]
// M=8192, K=256, N=512. Grid (4, 128) = (N/128, M/64), 256 threads.
// Also zeroes the k_rnn barrier counters (stream-ordered before k_rnn).
// ============================================================================
__global__ void __launch_bounds__(256) k_xproj(const int* __restrict__ x,
                                               const float* __restrict__ emb,
                                               const float* __restrict__ Wh,
                                               const float* __restrict__ bh)
{
    __shared__ float As[64][36];    // [row][k], padded, 16B-aligned rows
    __shared__ float Bs[32][132];   // [k][col], padded
    __shared__ int   xs[64];

    const int tid = threadIdx.x;
    const int m0  = blockIdx.y * 64;
    const int n0  = blockIdx.x * 128;

    if (blockIdx.x == 0 && blockIdx.y == 0 && tid < 8) g_cnt[tid] = 0;

    if (tid < 64) xs[tid] = x[m0 + tid];
    __syncthreads();

    const int ty = tid >> 5;   // 0..7  row octet
    const int tx = tid & 31;   // 0..31 col quad

    float acc[8][4];
#pragma unroll
    for (int i = 0; i < 8; i++)
#pragma unroll
        for (int j = 0; j < 4; j++) acc[i][j] = 0.f;

    for (int k0 = 0; k0 < EMB; k0 += 32) {
#pragma unroll
        for (int q = 0; q < 2; q++) {           // A: 64x32 = 512 float4
            int f = tid + q * 256;
            int r = f >> 3, c4 = f & 7;
            float4 v = *(const float4*)(emb + (size_t)xs[r] * EMB + k0 + c4 * 4);
            *(float4*)(&As[r][c4 * 4]) = v;
        }
#pragma unroll
        for (int q = 0; q < 4; q++) {           // B: 32x128 = 1024 float4
            int f = tid + q * 256;
            int r = f >> 5, c4 = f & 31;
            float4 v = *(const float4*)(Wh + (size_t)(k0 + r) * LAT + n0 + c4 * 4);
            *(float4*)(&Bs[r][c4 * 4]) = v;
        }
        __syncthreads();

#pragma unroll
        for (int kq = 0; kq < 8; kq++) {
            float bt[4][4];
#pragma unroll
            for (int kk = 0; kk < 4; kk++) {
                float4 t = *(float4*)(&Bs[kq * 4 + kk][tx * 4]);
                bt[kk][0] = t.x; bt[kk][1] = t.y; bt[kk][2] = t.z; bt[kk][3] = t.w;
            }
#pragma unroll
            for (int i = 0; i < 8; i++) {
                float4 a4 = *(float4*)(&As[ty * 8 + i][kq * 4]);
#pragma unroll
                for (int j = 0; j < 4; j++) {
                    acc[i][j] = fmaf(a4.x, bt[0][j],
                                fmaf(a4.y, bt[1][j],
                                fmaf(a4.z, bt[2][j],
                                fmaf(a4.w, bt[3][j], acc[i][j]))));
                }
            }
        }
        __syncthreads();
    }

    float4 bh4 = *(const float4*)(bh + n0 + tx * 4);
#pragma unroll
    for (int i = 0; i < 8; i++) {
        float4 o;
        o.x = acc[i][0] + bh4.x;
        o.y = acc[i][1] + bh4.y;
        o.z = acc[i][2] + bh4.z;
        o.w = acc[i][3] + bh4.w;
        *(float4*)(g_xproj + (size_t)(m0 + ty * 8 + i) * LAT + n0 + tx * 4) = o;
    }
}

// ============================================================================
// Kernel 2: persistent recurrence. h[t] = relu(xproj[t] + h[t-1] @ W_hh)
// 128 CTAs = 8 batch-groups (4 batches) x 16 col-groups (32 cols).
// 256 threads = 8 k-slices (s) x 32 cols (c). W_hh slice in registers.
// h[t-1] staged transposed in smem as packed f32x2 pairs -> fma.rn.f32x2.
// Per-group barrier: fence + atomic generation counter (16 arrivals/step).
// ============================================================================
__global__ void __launch_bounds__(256, 1) k_rnn(const float* __restrict__ Wh,
                                                float* __restrict__ hid)
{
    __shared__ ulonglong2 hsT[512];      // [k] -> {pack(b0,b1), pack(b2,b3)}
    __shared__ float      red[8][4][32]; // [slice][batch][col]

    const int tid  = threadIdx.x;
    const int s    = tid >> 5;           // 0..7  k-slice of 64
    const int c    = tid & 31;           // 0..31 local column
    const int bgrp = blockIdx.x >> 4;    // 0..7
    const int cgrp = blockIdx.x & 15;    // 0..15
    const int b0   = bgrp * 4;
    const int col  = cgrp * 32 + c;

    float w[64];
#pragma unroll
    for (int i = 0; i < 64; i++)
        w[i] = Wh[(size_t)(EMB + s * 64 + i) * LAT + col];

    unsigned target = 0;
    for (int t = 0; t < T_STEPS; t++) {
        // ---- stage h_{t-1} transposed into smem ----
#pragma unroll
        for (int hq = 0; hq < 2; hq++) {
            int k = tid + hq * 256;
            float v0, v1, v2, v3;
            if (t == 0) {
                v0 = v1 = v2 = v3 = 0.f;
            } else {
                const float* hp = hid + (size_t)((t - 1) * BATCH + b0) * LAT + k;
                v0 = __ldcg(hp);
                v1 = __ldcg(hp + LAT);
                v2 = __ldcg(hp + 2 * LAT);
                v3 = __ldcg(hp + 3 * LAT);
            }
            hsT[k] = make_ulonglong2(pack2(v0, v1), pack2(v2, v3));
        }
        __syncthreads();

        // ---- partial matvec: 64 k-values, 4 batches, 1 col ----
        unsigned long long acc01 = 0ull, acc23 = 0ull;
        const ulonglong2* hp = hsT + s * 64;
#pragma unroll
        for (int i = 0; i < 64; i++) {
            ulonglong2 hv = hp[i];
            unsigned long long w2 = pack2(w[i], w[i]);
            ffma2(acc01, hv.x, w2);
            ffma2(acc23, hv.y, w2);
        }
        float a0, a1, a2, a3;
        unpack2(acc01, a0, a1);
        unpack2(acc23, a2, a3);
        red[s][0][c] = a0;
        red[s][1][c] = a1;
        red[s][2][c] = a2;
        red[s][3][c] = a3;
        __syncthreads();

        // ---- reduce 8 slices, add xproj, relu, write h_t ----
        if (tid < 128) {
            int bb = tid >> 5, cc = tid & 31;
            float v = 0.f;
#pragma unroll
            for (int ss = 0; ss < 8; ss++) v += red[ss][bb][cc];
            int colw = cgrp * 32 + cc;
            size_t row = (size_t)(t * BATCH + b0 + bb);
            v += g_xproj[row * LAT + colw];
            v = fmaxf(v, 0.f);
            hid[row * LAT + colw] = v;
            __threadfence();
        }
        __syncthreads();

        // ---- group barrier (16 CTAs per batch-group) ----
        target += 16;
        if (tid == 0) {
            atomicAdd(&g_cnt[bgrp], 1u);
            while (*((volatile unsigned*)&g_cnt[bgrp]) < target) {
                __nanosleep(32);
            }
            __threadfence();
        }
        __syncthreads();
    }
}

// ============================================================================
// Kernel 3: out[M, OUT] = hid[M, LAT] @ Wo[LAT, OUT] + bo   (tf32 mma)
// CTA tile 128x128, BK=32, 2-stage cp.async, 8 warps (2m x 4n), warp 64x32.
// Grid (64, 250) = (M/128, OUT/128).
// ============================================================================
#define BM 128
#define BN 128
#define BK 32
#define A_ST 36
#define B_ST 136
#define A_TILE (BM * A_ST)                    // 4608 floats
#define B_TILE (BK * B_ST)                    // 4352 floats
#define SMEM_BYTES (2 * (A_TILE + B_TILE) * 4) // 71680 B

__global__ void __launch_bounds__(256, 1) k_out(const float* __restrict__ hid,
                                                const float* __restrict__ Wo,
                                                const float* __restrict__ bo,
                                                float* __restrict__ out)
{
    extern __shared__ float sm[];
    float* Apan = sm;                 // [2][BM][A_ST]
    float* Bpan = sm + 2 * A_TILE;    // [2][BK][B_ST]

    const int tid  = threadIdx.x;
    const int m0   = blockIdx.x * BM;
    const int n0   = blockIdx.y * BN;
    const int lane = tid & 31;
    const int warp = tid >> 5;
    const int wm   = warp >> 2;       // 0..1
    const int wn   = warp & 3;        // 0..3

    float acc[4][4][4];
#pragma unroll
    for (int mi = 0; mi < 4; mi++)
#pragma unroll
        for (int ni = 0; ni < 4; ni++)
#pragma unroll
            for (int j = 0; j < 4; j++) acc[mi][ni][j] = 0.f;

    auto load_stage = [&](int st, int k0) {
#pragma unroll
        for (int q = 0; q < 4; q++) {          // A: 128x32 = 1024 float4
            int idx = tid + q * 256;
            int r = idx >> 3, cc = (idx & 7) * 4;
            cp_async16(smaddr(Apan + (size_t)st * A_TILE + r * A_ST + cc),
                       hid + (size_t)(m0 + r) * LAT + k0 + cc);
        }
#pragma unroll
        for (int q = 0; q < 4; q++) {          // B: 32x128 = 1024 float4
            int idx = tid + q * 256;
            int r = idx >> 5, cc = (idx & 31) * 4;
            cp_async16(smaddr(Bpan + (size_t)st * B_TILE + r * B_ST + cc),
                       Wo + (size_t)(k0 + r) * OUT_DIM + n0 + cc);
        }
        cp_commit();
    };

    load_stage(0, 0);

#pragma unroll 1
    for (int kt = 0; kt < LAT / BK; kt++) {
        if (kt < LAT / BK - 1) {
            load_stage((kt + 1) & 1, (kt + 1) * BK);
            cp_wait<1>();
        } else {
            cp_wait<0>();
        }
        __syncthreads();

        const float* As = Apan + (size_t)(kt & 1) * A_TILE;
        const float* Bs = Bpan + (size_t)(kt & 1) * B_TILE;

#pragma unroll
        for (int kk = 0; kk < 4; kk++) {
            uint32_t af[4][4];
#pragma unroll
            for (int mi = 0; mi < 4; mi++) {
                int r = wm * 64 + mi * 16 + (lane >> 2);
                int k = kk * 8 + (lane & 3);
                const float* Ab = As + r * A_ST + k;
                af[mi][0] = cvt_tf32(Ab[0]);
                af[mi][1] = cvt_tf32(Ab[8 * A_ST]);
                af[mi][2] = cvt_tf32(Ab[4]);
                af[mi][3] = cvt_tf32(Ab[8 * A_ST + 4]);
            }
            uint32_t bf[4][2];
#pragma unroll
            for (int ni = 0; ni < 4; ni++) {
                int k = kk * 8 + (lane & 3);
                int cc = wn * 32 + ni * 8 + (lane >> 2);
                const float* Bb = Bs + k * B_ST + cc;
                bf[ni][0] = cvt_tf32(Bb[0]);
                bf[ni][1] = cvt_tf32(Bb[4 * B_ST]);
            }
#pragma unroll
            for (int mi = 0; mi < 4; mi++)
#pragma unroll
                for (int ni = 0; ni < 4; ni++)
                    mma_tf32(acc[mi][ni][0], acc[mi][ni][1],
                             acc[mi][ni][2], acc[mi][ni][3],
                             af[mi][0], af[mi][1], af[mi][2], af[mi][3],
                             bf[ni][0], bf[ni][1]);
        }
        __syncthreads();
    }

    // ---- epilogue: + bias, store fp32 ----
#pragma unroll
    for (int mi = 0; mi < 4; mi++) {
#pragma unroll
        for (int ni = 0; ni < 4; ni++) {
            int r = m0 + wm * 64 + mi * 16 + (lane >> 2);
            int cc = n0 + wn * 32 + ni * 8 + (lane & 3) * 2;
            float2 b2 = *(const float2*)(bo + cc);
            float2 o0, o1;
            o0.x = acc[mi][ni][0] + b2.x;
            o0.y = acc[mi][ni][1] + b2.y;
            o1.x = acc[mi][ni][2] + b2.x;
            o1.y = acc[mi][ni][3] + b2.y;
            *(float2*)(out + (size_t)r * OUT_DIM + cc)       = o0;
            *(float2*)(out + (size_t)(r + 8) * OUT_DIM + cc) = o1;
        }
    }
}

// ============================================================================
extern "C" void kernel_launch(void* const* d_in, const int* in_sizes, int n_in,
                              void* d_out, int out_size)
{
    (void)in_sizes; (void)n_in; (void)out_size;
    const int*   x   = (const int*)d_in[0];
    const float* emb = (const float*)d_in[1];
    const float* Wh  = (const float*)d_in[2];
    const float* bh  = (const float*)d_in[3];
    const float* Wo  = (const float*)d_in[4];
    const float* bo  = (const float*)d_in[5];

    float* out = (float*)d_out;                       // [8192, 32000]
    float* hid = out + (size_t)MROWS * OUT_DIM;       // [8192, 512]

    cudaFuncSetAttribute(k_out, cudaFuncAttributeMaxDynamicSharedMemorySize,
                         SMEM_BYTES);

    k_xproj<<<dim3(4, 128), 256>>>(x, emb, Wh, bh);
    k_rnn<<<128, 256>>>(Wh, hid);
    k_out<<<dim3(64, 250), 256, SMEM_BYTES>>>(hid, Wo, bo, out);
}

// round 4
// speedup vs baseline: 1.2036x; 1.2036x over previous
#include <cuda_runtime.h>
#include <cstdint>
#include <cstddef>

#define T_STEPS 256
#define BATCH   32
#define EMB     256
#define LAT     512
#define OUT_DIM 32000
#define MROWS   (T_STEPS * BATCH)   // 8192

// ---------------- device scratch (no allocations allowed) ------------------
__device__ float    g_xproj[(size_t)MROWS * LAT];      // 16 MB
__device__ float    g_hA[(size_t)MROWS * LAT];         // 16 MB, A fragment-major (tf32)
__device__ float    g_WoB[(size_t)OUT_DIM * LAT];      // 65.5 MB, B fragment-major (tf32)
__device__ unsigned g_cnt[8];                           // rnn barrier counters

// ---------------- helpers ----------------------------------------------------
__device__ __forceinline__ unsigned long long pack2(float a, float b) {
    unsigned long long r;
    asm("mov.b64 %0, {%1, %2};" : "=l"(r) : "f"(a), "f"(b));
    return r;
}
__device__ __forceinline__ void unpack2(unsigned long long v, float& a, float& b) {
    asm("mov.b64 {%0, %1}, %2;" : "=f"(a), "=f"(b) : "l"(v));
}
__device__ __forceinline__ void ffma2(unsigned long long& acc, unsigned long long h,
                                      unsigned long long w) {
    asm("fma.rn.f32x2 %0, %1, %2, %0;" : "+l"(acc) : "l"(h), "l"(w));
}
__device__ __forceinline__ float to_tf32(float f) {
    uint32_t o;
    asm("cvt.rna.tf32.f32 %0, %1;" : "=r"(o) : "f"(f));
    return __uint_as_float(o);
}
__device__ __forceinline__ uint32_t smaddr(const void* p) {
    return (uint32_t)__cvta_generic_to_shared(p);
}
__device__ __forceinline__ uint32_t elect_one_pred() {
    uint32_t pred;
    asm volatile(
        "{\n\t.reg .pred p;\n\t"
        "elect.sync _|p, 0xFFFFFFFF;\n\t"
        "selp.b32 %0, 1, 0, p;\n\t}"
        : "=r"(pred));
    return pred;
}
__device__ __forceinline__ void lds128(uint32_t a, uint32_t& r0, uint32_t& r1,
                                       uint32_t& r2, uint32_t& r3) {
    asm volatile("ld.shared.v4.b32 {%0, %1, %2, %3}, [%4];"
                 : "=r"(r0), "=r"(r1), "=r"(r2), "=r"(r3) : "r"(a));
}
__device__ __forceinline__ void bulk_g2s(uint32_t dst, const void* src,
                                         uint32_t bytes, uint32_t mbar) {
    asm volatile(
        "cp.async.bulk.shared::cluster.global.mbarrier::complete_tx::bytes "
        "[%0], [%1], %2, [%3];"
        :: "r"(dst), "l"(src), "r"(bytes), "r"(mbar) : "memory");
}
#define MBARRIER_INIT(mbar, cnt) \
    asm volatile("mbarrier.init.shared.b64 [%0], %1;" \
                 :: "r"((uint32_t)(mbar)), "r"((uint32_t)(cnt)) : "memory")
#define MBARRIER_ARRIVE(mbar) \
    asm volatile("mbarrier.arrive.shared.b64 _, [%0];" \
                 :: "r"((uint32_t)(mbar)) : "memory")
#define MBARRIER_EXPECT_TX(mbar, tx) \
    asm volatile("mbarrier.arrive.expect_tx.shared.b64 _, [%0], %1;" \
                 :: "r"((uint32_t)(mbar)), "r"((uint32_t)(tx)) : "memory")
#define MBARRIER_WAIT_PARITY(mbar, par) do {                                   \
    uint32_t _m = (uint32_t)(mbar);                                            \
    uint32_t _p = (uint32_t)(par);                                             \
    asm volatile(                                                              \
        "{\n\t.reg .pred P1;\n\t"                                              \
        "WL_%=:\n\t"                                                           \
        "mbarrier.try_wait.parity.acquire.cta.shared::cta.b64 P1, [%0], %1, 0x989680;\n\t" \
        "@P1 bra.uni WD_%=;\n\t"                                               \
        "bra.uni WL_%=;\n\t"                                                   \
        "WD_%=:\n\t}"                                                          \
        :: "r"(_m), "r"(_p) : "memory");                                       \
} while (0)
#define FENCE_ASYNC_SHARED() asm volatile("fence.proxy.async.shared::cta;" ::: "memory")

__device__ __forceinline__ void mma_tf32(float& c0, float& c1, float& c2, float& c3,
                                         uint32_t a0, uint32_t a1, uint32_t a2, uint32_t a3,
                                         uint32_t b0, uint32_t b1) {
    asm volatile(
        "mma.sync.aligned.m16n8k8.row.col.f32.tf32.tf32.f32 "
        "{%0,%1,%2,%3}, {%4,%5,%6,%7}, {%8,%9}, {%0,%1,%2,%3};"
        : "+f"(c0), "+f"(c1), "+f"(c2), "+f"(c3)
        : "r"(a0), "r"(a1), "r"(a2), "r"(a3), "r"(b0), "r"(b1));
}

// Fragment-major index for A value at (row m, col k), tf32, m16n8k8 layout.
__device__ __forceinline__ size_t hA_index(int m, int k) {
    int mt = m >> 7, mi16 = (m >> 4) & 7, r = m & 15;
    int kt = k >> 5, kk = (k >> 3) & 3, kb = k & 7;
    int lane = (r & 7) * 4 + (kb & 3);
    int j = (r >> 3) + 2 * (kb >> 2);
    return ((size_t)mt * 16 + kt) * 4096 + (size_t)((mi16 * 4 + kk) * 128 + lane * 4 + j);
}

// ============================================================================
// Kernel 1: xproj = gather(emb, x) @ W_h[:256] + b_h  (fp32 SIMT)
// ============================================================================
__global__ void __launch_bounds__(256) k_xproj(const int* __restrict__ x,
                                               const float* __restrict__ emb,
                                               const float* __restrict__ Wh,
                                               const float* __restrict__ bh)
{
    __shared__ float As[64][36];
    __shared__ float Bs[32][132];
    __shared__ int   xs[64];

    const int tid = threadIdx.x;
    const int m0  = blockIdx.y * 64;
    const int n0  = blockIdx.x * 128;

    if (blockIdx.x == 0 && blockIdx.y == 0 && tid < 8) g_cnt[tid] = 0;

    if (tid < 64) xs[tid] = x[m0 + tid];
    __syncthreads();

    const int ty = tid >> 5;
    const int tx = tid & 31;

    float acc[8][4];
#pragma unroll
    for (int i = 0; i < 8; i++)
#pragma unroll
        for (int j = 0; j < 4; j++) acc[i][j] = 0.f;

    for (int k0 = 0; k0 < EMB; k0 += 32) {
#pragma unroll
        for (int q = 0; q < 2; q++) {
            int f = tid + q * 256;
            int r = f >> 3, c4 = f & 7;
            float4 v = *(const float4*)(emb + (size_t)xs[r] * EMB + k0 + c4 * 4);
            *(float4*)(&As[r][c4 * 4]) = v;
        }
#pragma unroll
        for (int q = 0; q < 4; q++) {
            int f = tid + q * 256;
            int r = f >> 5, c4 = f & 31;
            float4 v = *(const float4*)(Wh + (size_t)(k0 + r) * LAT + n0 + c4 * 4);
            *(float4*)(&Bs[r][c4 * 4]) = v;
        }
        __syncthreads();

#pragma unroll
        for (int kq = 0; kq < 8; kq++) {
            float bt[4][4];
#pragma unroll
            for (int kk = 0; kk < 4; kk++) {
                float4 t = *(float4*)(&Bs[kq * 4 + kk][tx * 4]);
                bt[kk][0] = t.x; bt[kk][1] = t.y; bt[kk][2] = t.z; bt[kk][3] = t.w;
            }
#pragma unroll
            for (int i = 0; i < 8; i++) {
                float4 a4 = *(float4*)(&As[ty * 8 + i][kq * 4]);
#pragma unroll
                for (int j = 0; j < 4; j++) {
                    acc[i][j] = fmaf(a4.x, bt[0][j],
                                fmaf(a4.y, bt[1][j],
                                fmaf(a4.z, bt[2][j],
                                fmaf(a4.w, bt[3][j], acc[i][j]))));
                }
            }
        }
        __syncthreads();
    }

    float4 bh4 = *(const float4*)(bh + n0 + tx * 4);
#pragma unroll
    for (int i = 0; i < 8; i++) {
        float4 o;
        o.x = acc[i][0] + bh4.x;
        o.y = acc[i][1] + bh4.y;
        o.z = acc[i][2] + bh4.z;
        o.w = acc[i][3] + bh4.w;
        *(float4*)(g_xproj + (size_t)(m0 + ty * 8 + i) * LAT + n0 + tx * 4) = o;
    }
}

// ============================================================================
// Kernel 1b: build g_WoB — B fragment-major, tf32-converted.
// Panel [nt][kt] = 256n x 32k = 8192 floats. Grid (125, 16), 256 threads.
// Block b (0..63): wn=b>>4, kk=(b>>2)&3, np=b&3; 32 lanes x float4.
// float4 j: {B[k,n], B[k+4,n], B[k,n+8], B[k+4,n+8]}, k=lane&3 base, n=lane>>2.
// ============================================================================
__global__ void __launch_bounds__(256) k_prepB(const float* __restrict__ Wo)
{
    const int nt = blockIdx.x, kt = blockIdx.y;
    const int w = threadIdx.x >> 5, lane = threadIdx.x & 31;
    const size_t panel = ((size_t)nt * 16 + kt) * 8192;

#pragma unroll
    for (int bi = 0; bi < 8; bi++) {
        int b  = w * 8 + bi;
        int wn = b >> 4, kk = (b >> 2) & 3, np = b & 3;
        int k0 = kt * 32 + kk * 8 + (lane & 3);
        int n0 = nt * 256 + wn * 64 + np * 16 + (lane >> 2);
        const float* base = Wo + (size_t)k0 * OUT_DIM + n0;
        float4 v;
        v.x = to_tf32(base[0]);
        v.y = to_tf32(base[(size_t)4 * OUT_DIM]);
        v.z = to_tf32(base[8]);
        v.w = to_tf32(base[(size_t)4 * OUT_DIM + 8]);
        *(float4*)(g_WoB + panel + (size_t)b * 128 + lane * 4) = v;
    }
}

// ============================================================================
// Kernel 2: persistent recurrence. Also emits g_hA (fragment-major, tf32).
// ============================================================================
__global__ void __launch_bounds__(256, 1) k_rnn(const float* __restrict__ Wh,
                                                float* __restrict__ hid)
{
    __shared__ ulonglong2 hsT[512];
    __shared__ float      red[8][4][32];

    const int tid  = threadIdx.x;
    const int s    = tid >> 5;
    const int c    = tid & 31;
    const int bgrp = blockIdx.x >> 4;
    const int cgrp = blockIdx.x & 15;
    const int b0   = bgrp * 4;
    const int col  = cgrp * 32 + c;

    float w[64];
#pragma unroll
    for (int i = 0; i < 64; i++)
        w[i] = Wh[(size_t)(EMB + s * 64 + i) * LAT + col];

    unsigned target = 0;
    for (int t = 0; t < T_STEPS; t++) {
#pragma unroll
        for (int hq = 0; hq < 2; hq++) {
            int k = tid + hq * 256;
            float v0, v1, v2, v3;
            if (t == 0) {
                v0 = v1 = v2 = v3 = 0.f;
            } else {
                const float* hp = hid + (size_t)((t - 1) * BATCH + b0) * LAT + k;
                v0 = __ldcg(hp);
                v1 = __ldcg(hp + LAT);
                v2 = __ldcg(hp + 2 * LAT);
                v3 = __ldcg(hp + 3 * LAT);
            }
            hsT[k] = make_ulonglong2(pack2(v0, v1), pack2(v2, v3));
        }
        __syncthreads();

        unsigned long long acc01 = 0ull, acc23 = 0ull;
        const ulonglong2* hp = hsT + s * 64;
#pragma unroll
        for (int i = 0; i < 64; i++) {
            ulonglong2 hv = hp[i];
            unsigned long long w2 = pack2(w[i], w[i]);
            ffma2(acc01, hv.x, w2);
            ffma2(acc23, hv.y, w2);
        }
        float a0, a1, a2, a3;
        unpack2(acc01, a0, a1);
        unpack2(acc23, a2, a3);
        red[s][0][c] = a0;
        red[s][1][c] = a1;
        red[s][2][c] = a2;
        red[s][3][c] = a3;
        __syncthreads();

        if (tid < 128) {
            int bb = tid >> 5, cc = tid & 31;
            float v = 0.f;
#pragma unroll
            for (int ss = 0; ss < 8; ss++) v += red[ss][bb][cc];
            int colw = cgrp * 32 + cc;
            int rowi = t * BATCH + b0 + bb;
            size_t row = (size_t)rowi;
            v += g_xproj[row * LAT + colw];
            v = fmaxf(v, 0.f);
            hid[row * LAT + colw] = v;
            g_hA[hA_index(rowi, colw)] = to_tf32(v);
            __threadfence();
        }
        __syncthreads();

        target += 16;
        if (tid == 0) {
            atomicAdd(&g_cnt[bgrp], 1u);
            while (*((volatile unsigned*)&g_cnt[bgrp]) < target) {
                __nanosleep(32);
            }
            __threadfence();
        }
        __syncthreads();
    }
}

// ============================================================================
// Kernel 3: out = hid @ Wo + bo.  mma.sync tf32, fragment-major operands,
// cp.async.bulk 4-stage mbarrier ring. CTA tile 128m x 256n, BK=32.
// 8 warps (2m x 4n), warp tile 64x64. Grid (64 mt, 125 nt).
// ============================================================================
#define NSTG 4
#define A_PANEL_B 16384u
#define B_PANEL_B 32768u
#define STG_B (A_PANEL_B + B_PANEL_B)            // 49152
#define TILE_OFF 1024u
#define OUT_SMEM (TILE_OFF + NSTG * STG_B)       // 197632 B

__global__ void __launch_bounds__(256, 1) k_out_mma(const float* __restrict__ bo,
                                                    float* __restrict__ out)
{
    extern __shared__ char smem[];
    const uint32_t smem_base = smaddr(smem);
    const uint32_t fullb  = smem_base;           // 4 x 8B
    const uint32_t emptyb = smem_base + 32;      // 4 x 8B

    const int tid  = threadIdx.x;
    const int warp = tid >> 5;
    const int lane = tid & 31;
    const int wm   = warp >> 2;   // 0..1
    const int wn   = warp & 3;    // 0..3
    const int mt   = blockIdx.x;  // 0..63
    const int nt   = blockIdx.y;  // 0..124

    if (tid == 0) {
#pragma unroll
        for (int s2 = 0; s2 < NSTG; s2++) {
            MBARRIER_INIT(fullb  + s2 * 8, 1);
            MBARRIER_INIT(emptyb + s2 * 8, 8);
        }
        FENCE_ASYNC_SHARED();
    }
    __syncthreads();

    const float* gA = g_hA  + (size_t)mt * 16 * 4096;
    const float* gB = g_WoB + (size_t)nt * 16 * 8192;

    auto issue = [&](int cc) {
        int st = cc & 3;
        uint32_t sa = smem_base + TILE_OFF + st * STG_B;
        MBARRIER_EXPECT_TX(fullb + st * 8, STG_B);
        bulk_g2s(sa,             gA + (size_t)cc * 4096, A_PANEL_B, fullb + st * 8);
        bulk_g2s(sa + A_PANEL_B, gB + (size_t)cc * 8192, B_PANEL_B, fullb + st * 8);
    };

    if (tid == 0) {
        issue(0); issue(1); issue(2); issue(3);
    }

    float acc[4][8][4];
#pragma unroll
    for (int mi = 0; mi < 4; mi++)
#pragma unroll
        for (int ni = 0; ni < 8; ni++)
#pragma unroll
            for (int j = 0; j < 4; j++) acc[mi][ni][j] = 0.f;

#pragma unroll 1
    for (int c = 0; c < 16; c++) {
        const int st = c & 3;
        const int ph = (c >> 2) & 1;
        MBARRIER_WAIT_PARITY(fullb + st * 8, ph);

        const uint32_t sa = smem_base + TILE_OFF + st * STG_B;
        const uint32_t sb = sa + A_PANEL_B;

#pragma unroll
        for (int kk = 0; kk < 4; kk++) {
            uint32_t af[4][4];
#pragma unroll
            for (int mi = 0; mi < 4; mi++)
                lds128(sa + (uint32_t)(((wm * 4 + mi) * 4 + kk) * 512 + lane * 16),
                       af[mi][0], af[mi][1], af[mi][2], af[mi][3]);
            uint32_t bf[4][4];
#pragma unroll
            for (int np = 0; np < 4; np++)
                lds128(sb + (uint32_t)((((wn * 4 + kk) * 4) + np) * 512 + lane * 16),
                       bf[np][0], bf[np][1], bf[np][2], bf[np][3]);
#pragma unroll
            for (int mi = 0; mi < 4; mi++) {
#pragma unroll
                for (int np = 0; np < 4; np++) {
                    mma_tf32(acc[mi][2 * np][0], acc[mi][2 * np][1],
                             acc[mi][2 * np][2], acc[mi][2 * np][3],
                             af[mi][0], af[mi][1], af[mi][2], af[mi][3],
                             bf[np][0], bf[np][1]);
                    mma_tf32(acc[mi][2 * np + 1][0], acc[mi][2 * np + 1][1],
                             acc[mi][2 * np + 1][2], acc[mi][2 * np + 1][3],
                             af[mi][0], af[mi][1], af[mi][2], af[mi][3],
                             bf[np][2], bf[np][3]);
                }
            }
        }

        if (elect_one_pred()) MBARRIER_ARRIVE(emptyb + st * 8);
        if (tid == 0 && c < 12) {
            MBARRIER_WAIT_PARITY(emptyb + st * 8, ph);
            issue(c + 4);
        }
    }

    // ---- epilogue: direct register -> global stores, + bias ----
    const int m0 = mt * 128 + wm * 64;
    const int n0 = nt * 256 + wn * 64;
#pragma unroll
    for (int ni = 0; ni < 8; ni++) {
        int ccol = n0 + ni * 8 + (lane & 3) * 2;
        float2 b2 = *(const float2*)(bo + ccol);
#pragma unroll
        for (int mi = 0; mi < 4; mi++) {
            int r = m0 + mi * 16 + (lane >> 2);
            float2 o0, o1;
            o0.x = acc[mi][ni][0] + b2.x;
            o0.y = acc[mi][ni][1] + b2.y;
            o1.x = acc[mi][ni][2] + b2.x;
            o1.y = acc[mi][ni][3] + b2.y;
            *(float2*)(out + (size_t)r * OUT_DIM + ccol)       = o0;
            *(float2*)(out + (size_t)(r + 8) * OUT_DIM + ccol) = o1;
        }
    }
}

// ============================================================================
extern "C" void kernel_launch(void* const* d_in, const int* in_sizes, int n_in,
                              void* d_out, int out_size)
{
    (void)in_sizes; (void)n_in; (void)out_size;
    const int*   x   = (const int*)d_in[0];
    const float* emb = (const float*)d_in[1];
    const float* Wh  = (const float*)d_in[2];
    const float* bh  = (const float*)d_in[3];
    const float* Wo  = (const float*)d_in[4];
    const float* bo  = (const float*)d_in[5];

    float* out = (float*)d_out;                       // [8192, 32000]
    float* hid = out + (size_t)MROWS * OUT_DIM;       // [8192, 512]

    cudaFuncSetAttribute(k_out_mma, cudaFuncAttributeMaxDynamicSharedMemorySize,
                         OUT_SMEM);

    k_xproj<<<dim3(4, 128), 256>>>(x, emb, Wh, bh);
    k_prepB<<<dim3(OUT_DIM / 256, LAT / 32), 256>>>(Wo);
    k_rnn<<<128, 256>>>(Wh, hid);
    k_out_mma<<<dim3(MROWS / 128, OUT_DIM / 256), 256, OUT_SMEM>>>(bo, out);
}